// round 1
// baseline (speedup 1.0000x reference)
#include <cuda_runtime.h>
#include <math.h>

#define EMBED 768
#define NB    8
#define SEQ   1024
#define ROWS  (NB*SEQ)   // 8192
#define HID   1536

// Scratch (no allocations allowed -> __device__ globals)
__device__ float g_V[(size_t)ROWS*EMBED];   // x @ Wv          (25 MB)
__device__ float g_u[NB*EMBED];             // vsum, viewed as u[b, 768]
__device__ float g_w[NB*EMBED];             // LN(u)*g1+beta1  (per-batch constant)
__device__ float g_H[(size_t)ROWS*HID];     // gelu((x+w)@W1+b1) (50 MB)
__device__ float g_M[(size_t)ROWS*EMBED];   // gelu(H@W2+b2)   (25 MB)

// ---------------------------------------------------------------------------
// Tiled fp32 GEMM: C[M,N] = epi(A[M,K] @ B[K,N])
// BM=BN=128, BK=8, 256 threads, 8x8 per-thread microtile.
// ADD_W: A_eff[row,k] = A[row,k] + g_w[(row>>10)*768 + k]  (per-batch vector)
// BIAS / GELU: epilogue.
// Requires M%128==0, N%128==0, K%8==0 (true for all three calls).
// ---------------------------------------------------------------------------
template<bool ADD_W, bool BIAS, bool GELU>
__global__ __launch_bounds__(256)
void gemm_kernel(const float* __restrict__ A, const float* __restrict__ Bm,
                 const float* __restrict__ bias,
                 float* __restrict__ C, int M, int N, int K)
{
    __shared__ float As[8][128];
    __shared__ float Bs[8][128];

    const int tid = threadIdx.x;
    const int tm = tid >> 4;          // 0..15
    const int tn = tid & 15;          // 0..15
    const int rowBase = blockIdx.y * 128;
    const int colBase = blockIdx.x * 128;

    // A tile load mapping: 128 rows x 8 k, float4 per thread
    const int aRow  = tid >> 1;       // 0..127
    const int aCol4 = (tid & 1) * 4;  // 0 or 4
    // B tile load mapping: 8 k x 128 cols, float4 per thread
    const int bRow  = tid >> 5;       // 0..7
    const int bCol4 = (tid & 31) * 4; // 0..124

    const float* wrow = ADD_W ? (g_w + (size_t)(rowBase >> 10) * EMBED) : nullptr;

    float acc[8][8];
    #pragma unroll
    for (int i = 0; i < 8; i++)
        #pragma unroll
        for (int j = 0; j < 8; j++) acc[i][j] = 0.f;

    for (int k0 = 0; k0 < K; k0 += 8) {
        float4 av = *(const float4*)(A + (size_t)(rowBase + aRow) * K + k0 + aCol4);
        if (ADD_W) {
            float4 wv = *(const float4*)(wrow + k0 + aCol4);
            av.x += wv.x; av.y += wv.y; av.z += wv.z; av.w += wv.w;
        }
        As[aCol4 + 0][aRow] = av.x;
        As[aCol4 + 1][aRow] = av.y;
        As[aCol4 + 2][aRow] = av.z;
        As[aCol4 + 3][aRow] = av.w;

        *(float4*)&Bs[bRow][bCol4] =
            *(const float4*)(Bm + (size_t)(k0 + bRow) * N + colBase + bCol4);
        __syncthreads();

        #pragma unroll
        for (int kk = 0; kk < 8; kk++) {
            float a[8], b[8];
            #pragma unroll
            for (int i = 0; i < 8; i++) a[i] = As[kk][tm * 8 + i];
            #pragma unroll
            for (int j = 0; j < 8; j++) b[j] = Bs[kk][tn * 8 + j];
            #pragma unroll
            for (int i = 0; i < 8; i++)
                #pragma unroll
                for (int j = 0; j < 8; j++)
                    acc[i][j] += a[i] * b[j];
        }
        __syncthreads();
    }

    #pragma unroll
    for (int i = 0; i < 8; i++) {
        const size_t row = rowBase + tm * 8 + i;
        #pragma unroll
        for (int j = 0; j < 8; j++) {
            const int col = colBase + tn * 8 + j;
            float v = acc[i][j];
            if (BIAS) v += bias[col];
            if (GELU) v = 0.5f * v * (1.0f + erff(v * 0.70710678118654752f));
            C[row * N + col] = v;
        }
    }
}

// ---------------------------------------------------------------------------
// vsum[b,n,d] = sum_{s'=0..1023} V_chunk[b,n][64*s' + d]
// Chunk for (b,n) is contiguous: g_V + (b*12+n)*65536. One block per (b,n).
// ---------------------------------------------------------------------------
__global__ __launch_bounds__(512)
void vsum_kernel()
{
    const int bn  = blockIdx.x;        // 0..95 = b*12+n
    const int tid = threadIdx.x;       // 512
    const int d    = tid & 63;
    const int part = tid >> 6;         // 0..7
    const float* base = g_V + (size_t)bn * 65536;

    float s = 0.f;
    for (int sp = part; sp < 1024; sp += 8)
        s += base[sp * 64 + d];

    __shared__ float red[512];
    red[tid] = s;
    __syncthreads();
    if (part < 4) red[tid] += red[tid + 256];
    __syncthreads();
    if (part < 2) red[tid] += red[tid + 128];
    __syncthreads();
    if (part == 0) g_u[bn * 64 + d] = red[tid] + red[tid + 64];
}

// ---------------------------------------------------------------------------
// w[b,:] = LN(u[b,:]) * g1 + beta1   (one block per batch)
// ---------------------------------------------------------------------------
__global__ __launch_bounds__(256)
void ln_u_kernel(const float* __restrict__ g1, const float* __restrict__ be1)
{
    const int b   = blockIdx.x;
    const int tid = threadIdx.x;
    const float* u = g_u + b * EMBED;

    float x0 = u[tid], x1 = u[tid + 256], x2 = u[tid + 512];
    __shared__ float rs[256], rq[256];
    rs[tid] = x0 + x1 + x2;
    rq[tid] = x0 * x0 + x1 * x1 + x2 * x2;
    __syncthreads();
    for (int off = 128; off > 0; off >>= 1) {
        if (tid < off) { rs[tid] += rs[tid + off]; rq[tid] += rq[tid + off]; }
        __syncthreads();
    }
    __shared__ float s_mu, s_rstd;
    if (tid == 0) {
        float mu = rs[0] * (1.f / EMBED);
        float var = rq[0] * (1.f / EMBED) - mu * mu;
        s_mu = mu; s_rstd = rsqrtf(var + 1e-5f);
    }
    __syncthreads();
    float* w = g_w + b * EMBED;
    w[tid]       = (x0 - s_mu) * s_rstd * g1[tid]       + be1[tid];
    w[tid + 256] = (x1 - s_mu) * s_rstd * g1[tid + 256] + be1[tid + 256];
    w[tid + 512] = (x2 - s_mu) * s_rstd * g1[tid + 512] + be1[tid + 512];
}

// ---------------------------------------------------------------------------
// out[row,:] = x[row,:] + LN(M[row,:]) * g2 + beta2   (one block per row)
// ---------------------------------------------------------------------------
__global__ __launch_bounds__(256)
void final_kernel(const float* __restrict__ x, const float* __restrict__ g2,
                  const float* __restrict__ be2, float* __restrict__ out)
{
    const size_t row = blockIdx.x;
    const int tid = threadIdx.x;
    const float* mr = g_M + row * EMBED;
    const float* xr = x   + row * EMBED;

    float a0 = mr[tid], a1 = mr[tid + 256], a2 = mr[tid + 512];
    __shared__ float rs[256], rq[256];
    rs[tid] = a0 + a1 + a2;
    rq[tid] = a0 * a0 + a1 * a1 + a2 * a2;
    __syncthreads();
    for (int off = 128; off > 0; off >>= 1) {
        if (tid < off) { rs[tid] += rs[tid + off]; rq[tid] += rq[tid + off]; }
        __syncthreads();
    }
    __shared__ float s_mu, s_rstd;
    if (tid == 0) {
        float mu = rs[0] * (1.f / EMBED);
        float var = rq[0] * (1.f / EMBED) - mu * mu;
        s_mu = mu; s_rstd = rsqrtf(var + 1e-5f);
    }
    __syncthreads();
    float* o = out + row * EMBED;
    o[tid]       = xr[tid]       + (a0 - s_mu) * s_rstd * g2[tid]       + be2[tid];
    o[tid + 256] = xr[tid + 256] + (a1 - s_mu) * s_rstd * g2[tid + 256] + be2[tid + 256];
    o[tid + 512] = xr[tid + 512] + (a2 - s_mu) * s_rstd * g2[tid + 512] + be2[tid + 512];
}

// ---------------------------------------------------------------------------
extern "C" void kernel_launch(void* const* d_in, const int* in_sizes, int n_in,
                              void* d_out, int out_size)
{
    const float* x   = (const float*)d_in[0];
    // d_in[1]=Wq, d_in[2]=Wk : provably dead. softmax rows sum to 1 and the
    // einsum 'bnqk,bnvd->bnqd' factorizes into (sum_k attn)*(sum_v v).
    const float* Wv  = (const float*)d_in[3];
    const float* W1  = (const float*)d_in[4];
    const float* b1  = (const float*)d_in[5];
    const float* W2  = (const float*)d_in[6];
    const float* b2  = (const float*)d_in[7];
    const float* g1  = (const float*)d_in[8];
    const float* be1 = (const float*)d_in[9];
    const float* g2  = (const float*)d_in[10];
    const float* be2 = (const float*)d_in[11];
    float* out = (float*)d_out;

    float *pV, *pH, *pM;
    cudaGetSymbolAddress((void**)&pV, g_V);
    cudaGetSymbolAddress((void**)&pH, g_H);
    cudaGetSymbolAddress((void**)&pM, g_M);

    // 1) V = x @ Wv                      (8192 x 768 x 768)
    gemm_kernel<false, false, false><<<dim3(EMBED/128, ROWS/128), 256>>>(
        x, Wv, nullptr, pV, ROWS, EMBED, EMBED);

    // 2) u[b, n*64+d] = strided chunk reduction of V
    vsum_kernel<<<NB * 12, 512>>>();

    // 3) w[b,:] = LN(u[b,:]) * g1 + beta1
    ln_u_kernel<<<NB, 256>>>(g1, be1);

    // 4) H = gelu((x + w[b]) @ W1 + b1)  (8192 x 1536 x 768)
    gemm_kernel<true, true, true><<<dim3(HID/128, ROWS/128), 256>>>(
        x, W1, b1, pH, ROWS, HID, EMBED);

    // 5) M = gelu(H @ W2 + b2)           (8192 x 768 x 1536)
    gemm_kernel<false, true, true><<<dim3(EMBED/128, ROWS/128), 256>>>(
        pH, W2, b2, pM, ROWS, EMBED, HID);

    // 6) out = x + LN(M) * g2 + beta2
    final_kernel<<<ROWS, 256>>>(x, g2, be2, out);
}

// round 3
// speedup vs baseline: 2.7945x; 2.7945x over previous
#include <cuda_runtime.h>
#include <math.h>
#include <stdint.h>

#define EMBED 768
#define NB    8
#define SEQ   1024
#define ROWS  (NB*SEQ)   // 8192
#define HID   1536

// Scratch (no allocations allowed -> __device__ globals)
__device__ float g_V[(size_t)ROWS*EMBED];   // x @ Wv
__device__ float g_u[NB*EMBED];             // vsum per batch
__device__ float g_w[NB*EMBED];             // LN(u)*g1+beta1 (per-batch constant)
__device__ float g_H[(size_t)ROWS*HID];     // gelu((x+w)@W1+b1)
__device__ float g_M[(size_t)ROWS*EMBED];   // gelu(H@W2+b2)

// ---------------------------------------------------------------------------
// helpers
// ---------------------------------------------------------------------------
__device__ __forceinline__ float f_tf32(float f) {
    uint32_t r;
    asm("cvt.rna.tf32.f32 %0, %1;" : "=r"(r) : "f"(f));
    return __uint_as_float(r);
}

// exact-GELU via Abramowitz-Stegun 7.1.26 erf (abs err 1.5e-7)
__device__ __forceinline__ float gelu_f(float v) {
    float xs = v * 0.70710678118654752f;
    float ax = fabsf(xs);
    float t  = __frcp_rn(1.0f + 0.3275911f * ax);
    float poly = t * (0.254829592f + t * (-0.284496736f +
                 t * (1.421413741f + t * (-1.453152027f + t * 1.061405429f))));
    float erfv = 1.0f - poly * __expf(-ax * ax);
    erfv = copysignf(erfv, xs);
    return 0.5f * v * (1.0f + erfv);
}

__device__ __forceinline__ void mma_tf32(float c[4], const uint32_t a[4], const uint32_t b[2]) {
    asm volatile(
        "mma.sync.aligned.m16n8k8.row.col.f32.tf32.tf32.f32 "
        "{%0,%1,%2,%3}, {%4,%5,%6,%7}, {%8,%9}, {%0,%1,%2,%3};"
        : "+f"(c[0]), "+f"(c[1]), "+f"(c[2]), "+f"(c[3])
        : "r"(a[0]), "r"(a[1]), "r"(a[2]), "r"(a[3]), "r"(b[0]), "r"(b[1]));
}

// ---------------------------------------------------------------------------
// TF32 tensor-core GEMM: C[M,N] = epi(A[M,K] @ B[K,N])
// BM=BN=128, BK=16, 256 threads (8 warps 2x4), warp tile 64x32, mma m16n8k8.
// ADD_W: A_eff[row,k] = A[row,k] + g_w[(row>>10)*768 + k]
// ---------------------------------------------------------------------------
template<bool ADD_W, bool BIAS, bool GELU>
__global__ __launch_bounds__(256)
void gemm_tc(const float* __restrict__ A, const float* __restrict__ Bm,
             const float* __restrict__ bias, float* __restrict__ C,
             int M, int N, int K)
{
    __shared__ float As[128][20];   // [m][k], stride 20 -> conflict-free frags
    __shared__ float Bs[16][136];   // [k][n], stride 136 -> conflict-free frags

    const int tid  = threadIdx.x;
    const int lane = tid & 31;
    const int warp = tid >> 5;
    const int wm = (warp & 1) * 64;   // warp row offset within CTA tile
    const int wn = (warp >> 1) * 32;  // warp col offset
    const int rowBase = blockIdx.y * 128;
    const int colBase = blockIdx.x * 128;

    const float* wrow = ADD_W ? (g_w + (size_t)(rowBase >> 10) * EMBED) : nullptr;

    // load mappings (2 float4 each for A and B tiles)
    const int aR0 = (tid) >> 2,        aQ0 = (tid) & 3;
    const int aR1 = (tid + 256) >> 2,  aQ1 = (tid + 256) & 3;
    const int bR0 = (tid) >> 5,        bC0 = (tid) & 31;
    const int bR1 = (tid + 256) >> 5,  bC1 = (tid + 256) & 31;

    float acc[4][4][4];
    #pragma unroll
    for (int i = 0; i < 4; i++)
        #pragma unroll
        for (int j = 0; j < 4; j++)
            #pragma unroll
            for (int c = 0; c < 4; c++) acc[i][j][c] = 0.f;

    float4 aPre0, aPre1, bPre0, bPre1;

    // prefetch tile 0
    {
        aPre0 = *(const float4*)(A + (size_t)(rowBase + aR0) * K + aQ0 * 4);
        aPre1 = *(const float4*)(A + (size_t)(rowBase + aR1) * K + aQ1 * 4);
        if (ADD_W) {
            float4 w0 = *(const float4*)(wrow + aQ0 * 4);
            float4 w1 = *(const float4*)(wrow + aQ1 * 4);
            aPre0.x += w0.x; aPre0.y += w0.y; aPre0.z += w0.z; aPre0.w += w0.w;
            aPre1.x += w1.x; aPre1.y += w1.y; aPre1.z += w1.z; aPre1.w += w1.w;
        }
        bPre0 = *(const float4*)(Bm + (size_t)bR0 * N + colBase + bC0 * 4);
        bPre1 = *(const float4*)(Bm + (size_t)bR1 * N + colBase + bC1 * 4);
    }

    const int KT = K / 16;
    for (int t = 0; t < KT; t++) {
        // commit prefetched tile to smem (convert to tf32 once here)
        {
            float4 v;
            v = aPre0;
            As[aR0][aQ0*4+0] = f_tf32(v.x); As[aR0][aQ0*4+1] = f_tf32(v.y);
            As[aR0][aQ0*4+2] = f_tf32(v.z); As[aR0][aQ0*4+3] = f_tf32(v.w);
            v = aPre1;
            As[aR1][aQ1*4+0] = f_tf32(v.x); As[aR1][aQ1*4+1] = f_tf32(v.y);
            As[aR1][aQ1*4+2] = f_tf32(v.z); As[aR1][aQ1*4+3] = f_tf32(v.w);
            v = bPre0;
            Bs[bR0][bC0*4+0] = f_tf32(v.x); Bs[bR0][bC0*4+1] = f_tf32(v.y);
            Bs[bR0][bC0*4+2] = f_tf32(v.z); Bs[bR0][bC0*4+3] = f_tf32(v.w);
            v = bPre1;
            Bs[bR1][bC1*4+0] = f_tf32(v.x); Bs[bR1][bC1*4+1] = f_tf32(v.y);
            Bs[bR1][bC1*4+2] = f_tf32(v.z); Bs[bR1][bC1*4+3] = f_tf32(v.w);
        }
        __syncthreads();

        // prefetch next tile into registers (overlaps with compute below)
        if (t + 1 < KT) {
            const int kn = (t + 1) * 16;
            aPre0 = *(const float4*)(A + (size_t)(rowBase + aR0) * K + kn + aQ0 * 4);
            aPre1 = *(const float4*)(A + (size_t)(rowBase + aR1) * K + kn + aQ1 * 4);
            if (ADD_W) {
                float4 w0 = *(const float4*)(wrow + kn + aQ0 * 4);
                float4 w1 = *(const float4*)(wrow + kn + aQ1 * 4);
                aPre0.x += w0.x; aPre0.y += w0.y; aPre0.z += w0.z; aPre0.w += w0.w;
                aPre1.x += w1.x; aPre1.y += w1.y; aPre1.z += w1.z; aPre1.w += w1.w;
            }
            bPre0 = *(const float4*)(Bm + (size_t)(kn + bR0) * N + colBase + bC0 * 4);
            bPre1 = *(const float4*)(Bm + (size_t)(kn + bR1) * N + colBase + bC1 * 4);
        }

        // compute: 2 k-steps of 8
        #pragma unroll
        for (int ks = 0; ks < 16; ks += 8) {
            uint32_t afr[4][4];
            uint32_t bfr[4][2];
            #pragma unroll
            for (int mt = 0; mt < 4; mt++) {
                const int r = wm + mt * 16 + (lane >> 2);
                const int c = ks + (lane & 3);
                afr[mt][0] = __float_as_uint(As[r    ][c    ]);
                afr[mt][1] = __float_as_uint(As[r + 8][c    ]);
                afr[mt][2] = __float_as_uint(As[r    ][c + 4]);
                afr[mt][3] = __float_as_uint(As[r + 8][c + 4]);
            }
            #pragma unroll
            for (int nt = 0; nt < 4; nt++) {
                const int cc = wn + nt * 8 + (lane >> 2);
                const int rk = ks + (lane & 3);
                bfr[nt][0] = __float_as_uint(Bs[rk    ][cc]);
                bfr[nt][1] = __float_as_uint(Bs[rk + 4][cc]);
            }
            #pragma unroll
            for (int mt = 0; mt < 4; mt++)
                #pragma unroll
                for (int nt = 0; nt < 4; nt++)
                    mma_tf32(acc[mt][nt], afr[mt], bfr[nt]);
        }
        __syncthreads();
    }

    // epilogue
    #pragma unroll
    for (int mt = 0; mt < 4; mt++) {
        const int r0 = rowBase + wm + mt * 16 + (lane >> 2);
        #pragma unroll
        for (int nt = 0; nt < 4; nt++) {
            const int col = colBase + wn + nt * 8 + 2 * (lane & 3);
            float v0 = acc[mt][nt][0], v1 = acc[mt][nt][1];
            float v2 = acc[mt][nt][2], v3 = acc[mt][nt][3];
            if (BIAS) {
                float b0 = bias[col], b1 = bias[col + 1];
                v0 += b0; v1 += b1; v2 += b0; v3 += b1;
            }
            if (GELU) {
                v0 = gelu_f(v0); v1 = gelu_f(v1);
                v2 = gelu_f(v2); v3 = gelu_f(v3);
            }
            *(float2*)(C + (size_t)r0 * N + col)       = make_float2(v0, v1);
            *(float2*)(C + (size_t)(r0 + 8) * N + col) = make_float2(v2, v3);
        }
    }
}

// ---------------------------------------------------------------------------
// vsum[b,n,d] = sum_{s'} V_chunk[b,n][64*s' + d]; one block per (b,n)
// ---------------------------------------------------------------------------
__global__ __launch_bounds__(512)
void vsum_kernel()
{
    const int bn  = blockIdx.x;
    const int tid = threadIdx.x;
    const int d    = tid & 63;
    const int part = tid >> 6;
    const float* base = g_V + (size_t)bn * 65536;

    float s = 0.f;
    for (int sp = part; sp < 1024; sp += 8)
        s += base[sp * 64 + d];

    __shared__ float red[512];
    red[tid] = s;
    __syncthreads();
    if (part < 4) red[tid] += red[tid + 256];
    __syncthreads();
    if (part < 2) red[tid] += red[tid + 128];
    __syncthreads();
    if (part == 0) g_u[bn * 64 + d] = red[tid] + red[tid + 64];
}

// ---------------------------------------------------------------------------
// w[b,:] = LN(u[b,:]) * g1 + beta1
// ---------------------------------------------------------------------------
__global__ __launch_bounds__(256)
void ln_u_kernel(const float* __restrict__ g1, const float* __restrict__ be1)
{
    const int b   = blockIdx.x;
    const int tid = threadIdx.x;
    const float* u = g_u + b * EMBED;

    float x0 = u[tid], x1 = u[tid + 256], x2 = u[tid + 512];
    __shared__ float rs[256], rq[256];
    rs[tid] = x0 + x1 + x2;
    rq[tid] = x0 * x0 + x1 * x1 + x2 * x2;
    __syncthreads();
    for (int off = 128; off > 0; off >>= 1) {
        if (tid < off) { rs[tid] += rs[tid + off]; rq[tid] += rq[tid + off]; }
        __syncthreads();
    }
    __shared__ float s_mu, s_rstd;
    if (tid == 0) {
        float mu = rs[0] * (1.f / EMBED);
        float var = rq[0] * (1.f / EMBED) - mu * mu;
        s_mu = mu; s_rstd = rsqrtf(var + 1e-5f);
    }
    __syncthreads();
    float* w = g_w + b * EMBED;
    w[tid]       = (x0 - s_mu) * s_rstd * g1[tid]       + be1[tid];
    w[tid + 256] = (x1 - s_mu) * s_rstd * g1[tid + 256] + be1[tid + 256];
    w[tid + 512] = (x2 - s_mu) * s_rstd * g1[tid + 512] + be1[tid + 512];
}

// ---------------------------------------------------------------------------
// out[row,:] = x[row,:] + LN(M[row,:]) * g2 + beta2
// ---------------------------------------------------------------------------
__global__ __launch_bounds__(256)
void final_kernel(const float* __restrict__ x, const float* __restrict__ g2,
                  const float* __restrict__ be2, float* __restrict__ out)
{
    const size_t row = blockIdx.x;
    const int tid = threadIdx.x;
    const float* mr = g_M + row * EMBED;
    const float* xr = x   + row * EMBED;

    float a0 = mr[tid], a1 = mr[tid + 256], a2 = mr[tid + 512];
    __shared__ float rs[256], rq[256];
    rs[tid] = a0 + a1 + a2;
    rq[tid] = a0 * a0 + a1 * a1 + a2 * a2;
    __syncthreads();
    for (int off = 128; off > 0; off >>= 1) {
        if (tid < off) { rs[tid] += rs[tid + off]; rq[tid] += rq[tid + off]; }
        __syncthreads();
    }
    __shared__ float s_mu, s_rstd;
    if (tid == 0) {
        float mu = rs[0] * (1.f / EMBED);
        float var = rq[0] * (1.f / EMBED) - mu * mu;
        s_mu = mu; s_rstd = rsqrtf(var + 1e-5f);
    }
    __syncthreads();
    float* o = out + row * EMBED;
    o[tid]       = xr[tid]       + (a0 - s_mu) * s_rstd * g2[tid]       + be2[tid];
    o[tid + 256] = xr[tid + 256] + (a1 - s_mu) * s_rstd * g2[tid + 256] + be2[tid + 256];
    o[tid + 512] = xr[tid + 512] + (a2 - s_mu) * s_rstd * g2[tid + 512] + be2[tid + 512];
}

// ---------------------------------------------------------------------------
extern "C" void kernel_launch(void* const* d_in, const int* in_sizes, int n_in,
                              void* d_out, int out_size)
{
    const float* x   = (const float*)d_in[0];
    // d_in[1]=Wq, d_in[2]=Wk : provably dead (softmax rows sum to 1; the
    // einsum 'bnqk,bnvd->bnqd' factorizes into (sum_k attn)*(sum_v v)).
    const float* Wv  = (const float*)d_in[3];
    const float* W1  = (const float*)d_in[4];
    const float* b1  = (const float*)d_in[5];
    const float* W2  = (const float*)d_in[6];
    const float* b2  = (const float*)d_in[7];
    const float* g1  = (const float*)d_in[8];
    const float* be1 = (const float*)d_in[9];
    const float* g2  = (const float*)d_in[10];
    const float* be2 = (const float*)d_in[11];
    float* out = (float*)d_out;

    float *pV, *pH, *pM;
    cudaGetSymbolAddress((void**)&pV, g_V);
    cudaGetSymbolAddress((void**)&pH, g_H);
    cudaGetSymbolAddress((void**)&pM, g_M);

    // 1) V = x @ Wv                      (8192 x 768 x 768)
    gemm_tc<false, false, false><<<dim3(EMBED/128, ROWS/128), 256>>>(
        x, Wv, nullptr, pV, ROWS, EMBED, EMBED);

    // 2) u[b, n*64+d] = strided chunk reduction of V
    vsum_kernel<<<NB * 12, 512>>>();

    // 3) w[b,:] = LN(u[b,:]) * g1 + beta1
    ln_u_kernel<<<NB, 256>>>(g1, be1);

    // 4) H = gelu((x + w[b]) @ W1 + b1)  (8192 x 1536 x 768)
    gemm_tc<true, true, true><<<dim3(HID/128, ROWS/128), 256>>>(
        x, W1, b1, pH, ROWS, HID, EMBED);

    // 5) M = gelu(H @ W2 + b2)           (8192 x 768 x 1536)
    gemm_tc<false, true, true><<<dim3(EMBED/128, ROWS/128), 256>>>(
        pH, W2, b2, pM, ROWS, EMBED, HID);

    // 6) out = x + LN(M) * g2 + beta2
    final_kernel<<<ROWS, 256>>>(x, g2, be2, out);
}